// round 14
// baseline (speedup 1.0000x reference)
#include <cuda_runtime.h>
#include <cuda_fp16.h>
#include <math_constants.h>
#include <cstdint>

#define N_TOK    3072
#define D_MODEL  2048
#define N_HEADS  16
#define HEAD_DIM 128

// ---------------- device scratch (allocation-free rule) ----------------
// batched [2]: index 0 = query-side, 1 = key-side
__device__ __half g_in_hi[2][N_TOK * D_MODEL];
__device__ __half g_in_lo[2][N_TOK * D_MODEL];
__device__ __half g_w_hi[2][D_MODEL * D_MODEL];
__device__ __half g_w_lo[2][D_MODEL * D_MODEL];
__device__ __half g_out_hi[2][N_TOK * D_MODEL];
__device__ __half g_out_lo[2][N_TOK * D_MODEL];
__device__ int    g_cnt[N_HEADS * 24];   // per (head, row-block) completion counters

// ---------------- helpers ----------------
__device__ __forceinline__ uint32_t smem_u32(const void* p) {
    uint32_t a;
    asm("{ .reg .u64 t; cvta.to.shared.u64 t, %1; cvt.u32.u64 %0, t; }" : "=r"(a) : "l"(p));
    return a;
}
#define CP_ASYNC16(dst, src) \
    asm volatile("cp.async.cg.shared.global [%0], [%1], 16;" :: "r"(dst), "l"(src) : "memory")
#define CP_COMMIT() asm volatile("cp.async.commit_group;" ::: "memory")
#define CP_WAIT1()  asm volatile("cp.async.wait_group 1;" ::: "memory")
#define CP_WAIT0()  asm volatile("cp.async.wait_group 0;" ::: "memory")

#define LDSM_X4(r0, r1, r2, r3, addr) \
    asm volatile("ldmatrix.sync.aligned.m8n8.x4.shared.b16 {%0,%1,%2,%3}, [%4];" \
                 : "=r"(r0), "=r"(r1), "=r"(r2), "=r"(r3) : "r"(addr))

// m16n8k16 fp16 MMA, fp32 accumulate
__device__ __forceinline__ void mma_16816(float* d, const uint32_t* a, const uint32_t* b) {
    asm volatile(
        "mma.sync.aligned.m16n8k16.row.col.f32.f16.f16.f32 "
        "{%0,%1,%2,%3}, {%4,%5,%6,%7}, {%8,%9}, {%0,%1,%2,%3};"
        : "+f"(d[0]), "+f"(d[1]), "+f"(d[2]), "+f"(d[3])
        : "r"(a[0]), "r"(a[1]), "r"(a[2]), "r"(a[3]), "r"(b[0]), "r"(b[1]));
}

// ---------------- fused split: all four fp32 tensors -> fp16 hi/lo ----------------
#define ASZ ((size_t)N_TOK * D_MODEL)
#define WSZ ((size_t)D_MODEL * D_MODEL)
#define N4A (int)(ASZ / 4)
#define N4W (int)(WSZ / 4)

__global__ void split_all(const float* __restrict__ query, const float* __restrict__ key,
                          const float* __restrict__ Wq,    const float* __restrict__ Wk,
                          __half* __restrict__ inhi, __half* __restrict__ inlo,
                          __half* __restrict__ whi,  __half* __restrict__ wlo)
{
    int i = blockIdx.x * blockDim.x + threadIdx.x;
    const float* src; __half* hi; __half* lo; int base;
    if (i < N4A)                    { src = query; hi = inhi;           lo = inlo;           base = i; }
    else if (i < 2 * N4A)           { src = key;   hi = inhi + ASZ;     lo = inlo + ASZ;     base = i - N4A; }
    else if (i < 2 * N4A + N4W)     { src = Wq;    hi = whi;            lo = wlo;            base = i - 2 * N4A; }
    else if (i < 2 * (N4A + N4W))   { src = Wk;    hi = whi + WSZ;      lo = wlo + WSZ;      base = i - 2 * N4A - N4W; }
    else return;

    float4 v = ((const float4*)src)[base];
    __half h0 = __float2half_rn(v.x), h1 = __float2half_rn(v.y);
    __half h2 = __float2half_rn(v.z), h3 = __float2half_rn(v.w);
    __half l0 = __float2half_rn(v.x - __half2float(h0));
    __half l1 = __float2half_rn(v.y - __half2float(h1));
    __half l2 = __float2half_rn(v.z - __half2float(h2));
    __half l3 = __float2half_rn(v.w - __half2float(h3));
    __half2* hp = (__half2*)hi;
    __half2* lp = (__half2*)lo;
    hp[base * 2 + 0] = __half2(h0, h1);
    hp[base * 2 + 1] = __half2(h2, h3);
    lp[base * 2 + 0] = __half2(l0, l1);
    lp[base * 2 + 1] = __half2(l2, l3);
}

// ---------------- NT GEMM: C = A*B^T (+bias), fp16-split x 3-MMA ----------------
// CTA 128x256, 16 warps (2x8 grid of 64x32 warp tiles), BK=32, 3-stage ring.
// Energy path (Cf != null): completion-counter epilogue runs softmax in-kernel.
#define BM 128
#define BN 256
#define BK 32
#define RS 40                             // padded row stride (halves); 80B rows
#define ABYTES (BM * RS * 2)              // 10240 B per A tensor tile
#define BBYTES (BN * RS * 2)              // 20480 B per B tensor tile
#define STG_SZ (2 * ABYTES + 2 * BBYTES)  // 61440
#define SM_STG 1024                       // bias floats / sred / flag live here
#define GEMM_SMEM (SM_STG + 3 * STG_SZ)   // 185344 B
#define TILE16 (16 * RS * 2)              // byte stride of 16 rows = 1280

extern __shared__ char smem_raw[];

__global__ __launch_bounds__(512, 1)
void gemm_nt_mma(const __half* __restrict__ Ahi, const __half* __restrict__ Alo,
                 int lda, size_t aZ,
                 const __half* __restrict__ Bhi, const __half* __restrict__ Blo,
                 int ldb, size_t bZ,
                 const float* __restrict__ bias, const float* __restrict__ bias2,
                 float* __restrict__ Cf,
                 __half* __restrict__ Chi, __half* __restrict__ Clo,
                 int ldc, size_t cZ, int K)
{
    const int tid  = threadIdx.x;
    const int lane = tid & 31;
    const int wid  = tid >> 5;          // 0..15
    const int g    = lane >> 2;         // 0..7
    const int t    = lane & 3;          // 0..3
    const int wm   = (wid >> 3) * 64;   // warp row offset in CTA tile
    const int wn   = (wid & 7) * 32;    // warp col offset

    const int rowA0 = blockIdx.y * BM;
    const int rowB0 = blockIdx.x * BN;

    Ahi += (size_t)blockIdx.z * aZ;  Alo += (size_t)blockIdx.z * aZ;
    Bhi += (size_t)blockIdx.z * bZ;  Blo += (size_t)blockIdx.z * bZ;
    const float* biasz = (blockIdx.z && bias2) ? bias2 : bias;

    uint32_t sb = smem_u32(smem_raw);
    float* sbias = (float*)smem_raw;
    if (biasz && tid < BN) sbias[tid] = biasz[rowB0 + tid];

    // ldmatrix lane address offsets (bytes), relative to tensor tile base.
    const uint32_t aOff = (uint32_t)((wm + (lane & 15)) * RS + ((lane >> 4) << 3)) * 2;
    const int rfo = (lane & 7) + ((lane >> 1) & 8);   // (lane&16)?8:0
    const uint32_t bOff = (uint32_t)((wn + rfo) * RS + (lane & 8)) * 2;

    const int nc = K / BK;

    // fill one BK=32 chunk: A tensors 2x(128x4) + B tensors 2x(256x4) 16B chunks
    auto fill = [&](int c, int s) {
        uint32_t stBase = sb + SM_STG + s * STG_SZ;
        const __half* aSrc[2] = { Ahi + (size_t)rowA0 * lda + c * BK,
                                  Alo + (size_t)rowA0 * lda + c * BK };
        const __half* bSrc[2] = { Bhi + (size_t)rowB0 * ldb + c * BK,
                                  Blo + (size_t)rowB0 * ldb + c * BK };
#pragma unroll
        for (int rep = 0; rep < 2; rep++) {
            int idx = rep * 512 + tid;       // 0..1023
            int ten = idx >> 9;              // 0..1 (Ah, Al)
            int r   = (idx >> 2) & 127;
            int c16 = idx & 3;
            uint32_t dst = stBase + (uint32_t)(ten * ABYTES + r * (RS * 2) + c16 * 16);
            CP_ASYNC16(dst, aSrc[ten] + (size_t)r * lda + c16 * 8);
        }
#pragma unroll
        for (int rep = 0; rep < 4; rep++) {
            int idx = rep * 512 + tid;       // 0..2047
            int ten = idx >> 10;             // 0..1 (Bh, Bl)
            int r   = (idx >> 2) & 255;
            int c16 = idx & 3;
            uint32_t dst = stBase + (uint32_t)(2 * ABYTES + ten * BBYTES + r * (RS * 2) + c16 * 16);
            CP_ASYNC16(dst, bSrc[ten] + (size_t)r * ldb + c16 * 8);
        }
        CP_COMMIT();
    };

    fill(0, 0);
    if (nc > 1) fill(1, 1);

    float acc[4][4][4];
#pragma unroll
    for (int i = 0; i < 4; i++)
#pragma unroll
        for (int j = 0; j < 4; j++)
#pragma unroll
            for (int e = 0; e < 4; e++) acc[i][j][e] = 0.f;

    for (int c = 0; c < nc; c++) {
        if (c + 1 < nc) CP_WAIT1(); else CP_WAIT0();
        __syncthreads();                       // fill(c) visible; stage (c+2)%3 free
        if (c + 2 < nc) fill(c + 2, (c + 2) % 3);

        uint32_t stBase = sb + SM_STG + (c % 3) * STG_SZ;
        uint32_t bAh = stBase;
        uint32_t bAl = stBase + ABYTES;
        uint32_t bBh = stBase + 2 * ABYTES;
        uint32_t bBl = stBase + 2 * ABYTES + BBYTES;

#pragma unroll
        for (int ks = 0; ks < BK / 16; ks++) {
            uint32_t ah[4][4], al[4][4], bh[4][2], bl[4][2];
#pragma unroll
            for (int i = 0; i < 4; i++) {
                uint32_t off = aOff + i * TILE16 + ks * 32;
                LDSM_X4(ah[i][0], ah[i][1], ah[i][2], ah[i][3], bAh + off);
                LDSM_X4(al[i][0], al[i][1], al[i][2], al[i][3], bAl + off);
            }
#pragma unroll
            for (int jj = 0; jj < 2; jj++) {
                uint32_t off = bOff + jj * TILE16 + ks * 32;
                LDSM_X4(bh[2*jj][0], bh[2*jj][1], bh[2*jj+1][0], bh[2*jj+1][1], bBh + off);
                LDSM_X4(bl[2*jj][0], bl[2*jj][1], bl[2*jj+1][0], bl[2*jj+1][1], bBl + off);
            }
#pragma unroll
            for (int i = 0; i < 4; i++)
#pragma unroll
                for (int j = 0; j < 4; j++) {
                    mma_16816(acc[i][j], ah[i], bh[j]);
                    mma_16816(acc[i][j], ah[i], bl[j]);
                    mma_16816(acc[i][j], al[i], bh[j]);
                }
        }
    }

    // ---------------- epilogue ----------------
#pragma unroll
    for (int i = 0; i < 4; i++) {
#pragma unroll
        for (int j = 0; j < 4; j++) {
            int row = rowA0 + wm + i * 16 + g;
            int col = rowB0 + wn + j * 8 + 2 * t;
            if (Cf) {
                float* base = Cf + (size_t)blockIdx.z * cZ;
                float2 v0 = { acc[i][j][0], acc[i][j][1] };
                float2 v1 = { acc[i][j][2], acc[i][j][3] };
                *(float2*)(base + (size_t)row * ldc + col)       = v0;
                *(float2*)(base + (size_t)(row + 8) * ldc + col) = v1;
            } else {
                float b0 = biasz ? sbias[wn + j * 8 + 2 * t]     : 0.f;
                float b1 = biasz ? sbias[wn + j * 8 + 2 * t + 1] : 0.f;
                float x0 = acc[i][j][0] + b0, x1 = acc[i][j][1] + b1;
                float x2 = acc[i][j][2] + b0, x3 = acc[i][j][3] + b1;
                __half h0 = __float2half_rn(x0), h1 = __float2half_rn(x1);
                __half h2 = __float2half_rn(x2), h3 = __float2half_rn(x3);
                __half l0 = __float2half_rn(x0 - __half2float(h0));
                __half l1 = __float2half_rn(x1 - __half2float(h1));
                __half l2 = __float2half_rn(x2 - __half2float(h2));
                __half l3 = __float2half_rn(x3 - __half2float(h3));
                size_t zo = (size_t)blockIdx.z * cZ;
                size_t o0 = zo + (size_t)row * ldc + col;
                size_t o1 = zo + (size_t)(row + 8) * ldc + col;
                *(__half2*)(Chi + o0) = __half2(h0, h1);
                *(__half2*)(Chi + o1) = __half2(h2, h3);
                *(__half2*)(Clo + o0) = __half2(l0, l1);
                *(__half2*)(Clo + o1) = __half2(l2, l3);
            }
        }
    }

    // ---------------- fused softmax (energy path only) ----------------
    if (Cf) {
        __threadfence();                 // release: this thread's tile stores
        __syncthreads();                 // all threads' stores device-visible
        int* flag = (int*)(smem_raw + 512);
        if (tid == 0) {
            int* cnt = &g_cnt[blockIdx.z * gridDim.y + blockIdx.y];
            int old = atomicAdd(cnt, 1);
            int last = (old == (int)gridDim.x - 1);
            if (last) *cnt = 0;          // self-reset for next graph replay
            *flag = last;
        }
        __syncthreads();
        if (*flag) {
            __threadfence();             // acquire: see all 12 tiles
            float* base = Cf + (size_t)blockIdx.z * cZ + (size_t)rowA0 * ldc;
            const int half = tid >> 8;   // 0..1 : two 256-thread row groups
            const int htid = tid & 255;
            float (*sred)[8] = (float(*)[8])(smem_raw + 640);

            for (int rp = 0; rp < BM / 2; rp++) {
                float* p = base + (size_t)(rp * 2 + half) * ldc;
                float4 v[3];
                float mx = -CUDART_INF_F;
#pragma unroll
                for (int i = 0; i < 3; i++) {
                    v[i] = *(const float4*)(p + htid * 4 + i * 1024);
                    mx = fmaxf(mx, fmaxf(fmaxf(v[i].x, v[i].y), fmaxf(v[i].z, v[i].w)));
                }
#pragma unroll
                for (int o = 16; o; o >>= 1) mx = fmaxf(mx, __shfl_xor_sync(0xffffffffu, mx, o));
                if ((htid & 31) == 0) sred[half][htid >> 5] = mx;
                __syncthreads();
                {
                    float m = sred[half][htid & 7];
#pragma unroll
                    for (int o = 4; o; o >>= 1) m = fmaxf(m, __shfl_xor_sync(0xffffffffu, m, o));
                    mx = m;
                }
                __syncthreads();

                float sum = 0.f;
#pragma unroll
                for (int i = 0; i < 3; i++) {
                    v[i].x = __expf(v[i].x - mx); sum += v[i].x;
                    v[i].y = __expf(v[i].y - mx); sum += v[i].y;
                    v[i].z = __expf(v[i].z - mx); sum += v[i].z;
                    v[i].w = __expf(v[i].w - mx); sum += v[i].w;
                }
#pragma unroll
                for (int o = 16; o; o >>= 1) sum += __shfl_xor_sync(0xffffffffu, sum, o);
                if ((htid & 31) == 0) sred[half][htid >> 5] = sum;
                __syncthreads();
                {
                    float s = sred[half][htid & 7];
#pragma unroll
                    for (int o = 4; o; o >>= 1) s += __shfl_xor_sync(0xffffffffu, s, o);
                    sum = s;
                }

                const float inv = 1.0f / sum;
#pragma unroll
                for (int i = 0; i < 3; i++) {
                    v[i].x *= inv; v[i].y *= inv; v[i].z *= inv; v[i].w *= inv;
                    *(float4*)(p + htid * 4 + i * 1024) = v[i];
                }
                __syncthreads();         // protect sred before next iteration
            }
        }
    }
}

// ---------------- launcher ----------------
extern "C" void kernel_launch(void* const* d_in, const int* in_sizes, int n_in,
                              void* d_out, int out_size)
{
    const float* query = (const float*)d_in[0];
    const float* key   = (const float*)d_in[1];
    const float* Wq = (const float*)d_in[3];
    const float* bq = (const float*)d_in[4];
    const float* Wk = (const float*)d_in[5];
    const float* bk = (const float*)d_in[6];
    float* out = (float*)d_out;

    __half *inhi, *inlo, *whi, *wlo, *ohi, *olo;
    cudaGetSymbolAddress((void**)&inhi, g_in_hi);
    cudaGetSymbolAddress((void**)&inlo, g_in_lo);
    cudaGetSymbolAddress((void**)&whi,  g_w_hi);
    cudaGetSymbolAddress((void**)&wlo,  g_w_lo);
    cudaGetSymbolAddress((void**)&ohi,  g_out_hi);
    cudaGetSymbolAddress((void**)&olo,  g_out_lo);

    cudaFuncSetAttribute(gemm_nt_mma, cudaFuncAttributeMaxDynamicSharedMemorySize, GEMM_SMEM);

    // 1) fused split of all four fp32 tensors into fp16 hi/lo pairs
    {
        int total = 2 * N4A + 2 * N4W;
        split_all<<<(total + 255) / 256, 256>>>(query, key, Wq, Wk, inhi, inlo, whi, wlo);
    }
    // 2) merged projections: z=0 -> Q = query@Wq^T+bq, z=1 -> K = key@Wk^T+bk
    {
        dim3 grid(D_MODEL / BN, N_TOK / BM, 2);
        gemm_nt_mma<<<grid, 512, GEMM_SMEM>>>(inhi, inlo, D_MODEL, ASZ,
                                              whi,  wlo,  D_MODEL, WSZ,
                                              bq, bk,
                                              nullptr, ohi, olo, D_MODEL, ASZ, D_MODEL);
    }
    // 3) energy[h] = Q_h @ K_h^T -> fp32 scores + fused per-row-group softmax
    {
        dim3 grid(N_TOK / BN, N_TOK / BM, N_HEADS);
        gemm_nt_mma<<<grid, 512, GEMM_SMEM>>>(ohi,       olo,       D_MODEL, HEAD_DIM,
                                              ohi + ASZ, olo + ASZ, D_MODEL, HEAD_DIM,
                                              nullptr, nullptr,
                                              out, nullptr, nullptr,
                                              N_TOK, (size_t)N_TOK * N_TOK, HEAD_DIM);
    }
}

// round 15
// speedup vs baseline: 1.1774x; 1.1774x over previous
#include <cuda_runtime.h>
#include <cuda_fp16.h>
#include <math_constants.h>
#include <cstdint>

#define N_TOK    3072
#define D_MODEL  2048
#define N_HEADS  16
#define HEAD_DIM 128
#define NCHUNK   4
#define HPC      (N_HEADS / NCHUNK)   // heads per chunk = 4

// ---------------- device scratch (allocation-free rule) ----------------
// batched [2]: index 0 = query-side, 1 = key-side
__device__ __half g_in_hi[2][N_TOK * D_MODEL];
__device__ __half g_in_lo[2][N_TOK * D_MODEL];
__device__ __half g_w_hi[2][D_MODEL * D_MODEL];
__device__ __half g_w_lo[2][D_MODEL * D_MODEL];
__device__ __half g_out_hi[2][N_TOK * D_MODEL];
__device__ __half g_out_lo[2][N_TOK * D_MODEL];

// ---------------- second stream + events (pre-main init; no device mem) ----
static cudaStream_t g_s2;
static cudaEvent_t  g_evg[NCHUNK];
static cudaEvent_t  g_evs;
namespace {
struct StreamInit {
    StreamInit() {
        cudaStreamCreateWithFlags(&g_s2, cudaStreamNonBlocking);
        for (int i = 0; i < NCHUNK; i++)
            cudaEventCreateWithFlags(&g_evg[i], cudaEventDisableTiming);
        cudaEventCreateWithFlags(&g_evs, cudaEventDisableTiming);
    }
};
StreamInit g_stream_init;
}

// ---------------- helpers ----------------
__device__ __forceinline__ uint32_t smem_u32(const void* p) {
    uint32_t a;
    asm("{ .reg .u64 t; cvta.to.shared.u64 t, %1; cvt.u32.u64 %0, t; }" : "=r"(a) : "l"(p));
    return a;
}
#define CP_ASYNC16(dst, src) \
    asm volatile("cp.async.cg.shared.global [%0], [%1], 16;" :: "r"(dst), "l"(src) : "memory")
#define CP_COMMIT() asm volatile("cp.async.commit_group;" ::: "memory")
#define CP_WAIT1()  asm volatile("cp.async.wait_group 1;" ::: "memory")
#define CP_WAIT0()  asm volatile("cp.async.wait_group 0;" ::: "memory")

#define LDSM_X4(r0, r1, r2, r3, addr) \
    asm volatile("ldmatrix.sync.aligned.m8n8.x4.shared.b16 {%0,%1,%2,%3}, [%4];" \
                 : "=r"(r0), "=r"(r1), "=r"(r2), "=r"(r3) : "r"(addr))

// m16n8k16 fp16 MMA, fp32 accumulate
__device__ __forceinline__ void mma_16816(float* d, const uint32_t* a, const uint32_t* b) {
    asm volatile(
        "mma.sync.aligned.m16n8k16.row.col.f32.f16.f16.f32 "
        "{%0,%1,%2,%3}, {%4,%5,%6,%7}, {%8,%9}, {%0,%1,%2,%3};"
        : "+f"(d[0]), "+f"(d[1]), "+f"(d[2]), "+f"(d[3])
        : "r"(a[0]), "r"(a[1]), "r"(a[2]), "r"(a[3]), "r"(b[0]), "r"(b[1]));
}

// ---------------- fused split: all four fp32 tensors -> fp16 hi/lo ----------------
#define ASZ ((size_t)N_TOK * D_MODEL)
#define WSZ ((size_t)D_MODEL * D_MODEL)
#define N4A (int)(ASZ / 4)
#define N4W (int)(WSZ / 4)

__global__ void split_all(const float* __restrict__ query, const float* __restrict__ key,
                          const float* __restrict__ Wq,    const float* __restrict__ Wk,
                          __half* __restrict__ inhi, __half* __restrict__ inlo,
                          __half* __restrict__ whi,  __half* __restrict__ wlo)
{
    int i = blockIdx.x * blockDim.x + threadIdx.x;
    const float* src; __half* hi; __half* lo; int base;
    if (i < N4A)                    { src = query; hi = inhi;           lo = inlo;           base = i; }
    else if (i < 2 * N4A)           { src = key;   hi = inhi + ASZ;     lo = inlo + ASZ;     base = i - N4A; }
    else if (i < 2 * N4A + N4W)     { src = Wq;    hi = whi;            lo = wlo;            base = i - 2 * N4A; }
    else if (i < 2 * (N4A + N4W))   { src = Wk;    hi = whi + WSZ;      lo = wlo + WSZ;      base = i - 2 * N4A - N4W; }
    else return;

    float4 v = ((const float4*)src)[base];
    __half h0 = __float2half_rn(v.x), h1 = __float2half_rn(v.y);
    __half h2 = __float2half_rn(v.z), h3 = __float2half_rn(v.w);
    __half l0 = __float2half_rn(v.x - __half2float(h0));
    __half l1 = __float2half_rn(v.y - __half2float(h1));
    __half l2 = __float2half_rn(v.z - __half2float(h2));
    __half l3 = __float2half_rn(v.w - __half2float(h3));
    __half2* hp = (__half2*)hi;
    __half2* lp = (__half2*)lo;
    hp[base * 2 + 0] = __half2(h0, h1);
    hp[base * 2 + 1] = __half2(h2, h3);
    lp[base * 2 + 0] = __half2(l0, l1);
    lp[base * 2 + 1] = __half2(l2, l3);
}

// ---------------- NT GEMM: C = A*B^T (+bias), fp16-split x 3-MMA ----------------
// CTA 128x256, 16 warps (2x8 grid of 64x32 warp tiles), BK=32, 3-stage ring.
#define BM 128
#define BN 256
#define BK 32
#define RS 40                             // padded row stride (halves); 80B rows
#define ABYTES (BM * RS * 2)              // 10240 B per A tensor tile
#define BBYTES (BN * RS * 2)              // 20480 B per B tensor tile
#define STG_SZ (2 * ABYTES + 2 * BBYTES)  // 61440
#define SM_STG 1024                       // bias floats live in [0,1024)
#define GEMM_SMEM (SM_STG + 3 * STG_SZ)   // 185344 B
#define TILE16 (16 * RS * 2)              // byte stride of 16 rows = 1280

extern __shared__ char smem_raw[];

__global__ __launch_bounds__(512, 1)
void gemm_nt_mma(const __half* __restrict__ Ahi, const __half* __restrict__ Alo,
                 int lda, size_t aZ,
                 const __half* __restrict__ Bhi, const __half* __restrict__ Blo,
                 int ldb, size_t bZ,
                 const float* __restrict__ bias, const float* __restrict__ bias2,
                 float* __restrict__ Cf,
                 __half* __restrict__ Chi, __half* __restrict__ Clo,
                 int ldc, size_t cZ, int K)
{
    const int tid  = threadIdx.x;
    const int lane = tid & 31;
    const int wid  = tid >> 5;          // 0..15
    const int g    = lane >> 2;         // 0..7
    const int t    = lane & 3;          // 0..3
    const int wm   = (wid >> 3) * 64;   // warp row offset in CTA tile
    const int wn   = (wid & 7) * 32;    // warp col offset

    const int rowA0 = blockIdx.y * BM;
    const int rowB0 = blockIdx.x * BN;

    Ahi += (size_t)blockIdx.z * aZ;  Alo += (size_t)blockIdx.z * aZ;
    Bhi += (size_t)blockIdx.z * bZ;  Blo += (size_t)blockIdx.z * bZ;
    const float* biasz = (blockIdx.z && bias2) ? bias2 : bias;

    uint32_t sb = smem_u32(smem_raw);
    float* sbias = (float*)smem_raw;
    if (biasz && tid < BN) sbias[tid] = biasz[rowB0 + tid];

    // ldmatrix lane address offsets (bytes), relative to tensor tile base.
    const uint32_t aOff = (uint32_t)((wm + (lane & 15)) * RS + ((lane >> 4) << 3)) * 2;
    const int rfo = (lane & 7) + ((lane >> 1) & 8);   // (lane&16)?8:0
    const uint32_t bOff = (uint32_t)((wn + rfo) * RS + (lane & 8)) * 2;

    const int nc = K / BK;

    // fill one BK=32 chunk: A tensors 2x(128x4) + B tensors 2x(256x4) 16B chunks
    auto fill = [&](int c, int s) {
        uint32_t stBase = sb + SM_STG + s * STG_SZ;
        const __half* aSrc[2] = { Ahi + (size_t)rowA0 * lda + c * BK,
                                  Alo + (size_t)rowA0 * lda + c * BK };
        const __half* bSrc[2] = { Bhi + (size_t)rowB0 * ldb + c * BK,
                                  Blo + (size_t)rowB0 * ldb + c * BK };
#pragma unroll
        for (int rep = 0; rep < 2; rep++) {
            int idx = rep * 512 + tid;       // 0..1023
            int ten = idx >> 9;              // 0..1 (Ah, Al)
            int r   = (idx >> 2) & 127;
            int c16 = idx & 3;
            uint32_t dst = stBase + (uint32_t)(ten * ABYTES + r * (RS * 2) + c16 * 16);
            CP_ASYNC16(dst, aSrc[ten] + (size_t)r * lda + c16 * 8);
        }
#pragma unroll
        for (int rep = 0; rep < 4; rep++) {
            int idx = rep * 512 + tid;       // 0..2047
            int ten = idx >> 10;             // 0..1 (Bh, Bl)
            int r   = (idx >> 2) & 255;
            int c16 = idx & 3;
            uint32_t dst = stBase + (uint32_t)(2 * ABYTES + ten * BBYTES + r * (RS * 2) + c16 * 16);
            CP_ASYNC16(dst, bSrc[ten] + (size_t)r * ldb + c16 * 8);
        }
        CP_COMMIT();
    };

    fill(0, 0);
    if (nc > 1) fill(1, 1);

    float acc[4][4][4];
#pragma unroll
    for (int i = 0; i < 4; i++)
#pragma unroll
        for (int j = 0; j < 4; j++)
#pragma unroll
            for (int e = 0; e < 4; e++) acc[i][j][e] = 0.f;

    for (int c = 0; c < nc; c++) {
        if (c + 1 < nc) CP_WAIT1(); else CP_WAIT0();
        __syncthreads();                       // fill(c) visible; stage (c+2)%3 free
        if (c + 2 < nc) fill(c + 2, (c + 2) % 3);

        uint32_t stBase = sb + SM_STG + (c % 3) * STG_SZ;
        uint32_t bAh = stBase;
        uint32_t bAl = stBase + ABYTES;
        uint32_t bBh = stBase + 2 * ABYTES;
        uint32_t bBl = stBase + 2 * ABYTES + BBYTES;

#pragma unroll
        for (int ks = 0; ks < BK / 16; ks++) {
            uint32_t ah[4][4], al[4][4], bh[4][2], bl[4][2];
#pragma unroll
            for (int i = 0; i < 4; i++) {
                uint32_t off = aOff + i * TILE16 + ks * 32;
                LDSM_X4(ah[i][0], ah[i][1], ah[i][2], ah[i][3], bAh + off);
                LDSM_X4(al[i][0], al[i][1], al[i][2], al[i][3], bAl + off);
            }
#pragma unroll
            for (int jj = 0; jj < 2; jj++) {
                uint32_t off = bOff + jj * TILE16 + ks * 32;
                LDSM_X4(bh[2*jj][0], bh[2*jj][1], bh[2*jj+1][0], bh[2*jj+1][1], bBh + off);
                LDSM_X4(bl[2*jj][0], bl[2*jj][1], bl[2*jj+1][0], bl[2*jj+1][1], bBl + off);
            }
#pragma unroll
            for (int i = 0; i < 4; i++)
#pragma unroll
                for (int j = 0; j < 4; j++) {
                    mma_16816(acc[i][j], ah[i], bh[j]);
                    mma_16816(acc[i][j], ah[i], bl[j]);
                    mma_16816(acc[i][j], al[i], bh[j]);
                }
        }
    }

    // ---------------- epilogue ----------------
#pragma unroll
    for (int i = 0; i < 4; i++) {
#pragma unroll
        for (int j = 0; j < 4; j++) {
            int row = rowA0 + wm + i * 16 + g;
            int col = rowB0 + wn + j * 8 + 2 * t;
            if (Cf) {
                float* base = Cf + (size_t)blockIdx.z * cZ;
                float2 v0 = { acc[i][j][0], acc[i][j][1] };
                float2 v1 = { acc[i][j][2], acc[i][j][3] };
                *(float2*)(base + (size_t)row * ldc + col)       = v0;
                *(float2*)(base + (size_t)(row + 8) * ldc + col) = v1;
            } else {
                float b0 = biasz ? sbias[wn + j * 8 + 2 * t]     : 0.f;
                float b1 = biasz ? sbias[wn + j * 8 + 2 * t + 1] : 0.f;
                float x0 = acc[i][j][0] + b0, x1 = acc[i][j][1] + b1;
                float x2 = acc[i][j][2] + b0, x3 = acc[i][j][3] + b1;
                __half h0 = __float2half_rn(x0), h1 = __float2half_rn(x1);
                __half h2 = __float2half_rn(x2), h3 = __float2half_rn(x3);
                __half l0 = __float2half_rn(x0 - __half2float(h0));
                __half l1 = __float2half_rn(x1 - __half2float(h1));
                __half l2 = __float2half_rn(x2 - __half2float(h2));
                __half l3 = __float2half_rn(x3 - __half2float(h3));
                size_t zo = (size_t)blockIdx.z * cZ;
                size_t o0 = zo + (size_t)row * ldc + col;
                size_t o1 = zo + (size_t)(row + 8) * ldc + col;
                *(__half2*)(Chi + o0) = __half2(h0, h1);
                *(__half2*)(Chi + o1) = __half2(h2, h3);
                *(__half2*)(Clo + o0) = __half2(l0, l1);
                *(__half2*)(Clo + o1) = __half2(l2, l3);
            }
        }
    }
}

// ---------------- softmax: one block per row, row in registers ----------------
__global__ __launch_bounds__(256)
void softmax_rows(float* __restrict__ data)
{
    float* p = data + (size_t)blockIdx.x * N_TOK;
    const int tid = threadIdx.x;

    float4 v[3];
    float mx = -CUDART_INF_F;
#pragma unroll
    for (int i = 0; i < 3; i++) {
        v[i] = __ldcs((const float4*)(p + tid * 4 + i * 1024));
        mx = fmaxf(mx, fmaxf(fmaxf(v[i].x, v[i].y), fmaxf(v[i].z, v[i].w)));
    }

    __shared__ float sred[8];
#pragma unroll
    for (int o = 16; o; o >>= 1) mx = fmaxf(mx, __shfl_xor_sync(0xffffffffu, mx, o));
    if ((tid & 31) == 0) sred[tid >> 5] = mx;
    __syncthreads();
    {
        float m = sred[tid & 7];
#pragma unroll
        for (int o = 4; o; o >>= 1) m = fmaxf(m, __shfl_xor_sync(0xffffffffu, m, o));
        mx = m;
    }
    __syncthreads();

    float sum = 0.f;
#pragma unroll
    for (int i = 0; i < 3; i++) {
        v[i].x = __expf(v[i].x - mx); sum += v[i].x;
        v[i].y = __expf(v[i].y - mx); sum += v[i].y;
        v[i].z = __expf(v[i].z - mx); sum += v[i].z;
        v[i].w = __expf(v[i].w - mx); sum += v[i].w;
    }
#pragma unroll
    for (int o = 16; o; o >>= 1) sum += __shfl_xor_sync(0xffffffffu, sum, o);
    if ((tid & 31) == 0) sred[tid >> 5] = sum;
    __syncthreads();
    {
        float s = sred[tid & 7];
#pragma unroll
        for (int o = 4; o; o >>= 1) s += __shfl_xor_sync(0xffffffffu, s, o);
        sum = s;
    }

    const float inv = 1.0f / sum;
#pragma unroll
    for (int i = 0; i < 3; i++) {
        v[i].x *= inv; v[i].y *= inv; v[i].z *= inv; v[i].w *= inv;
        *(float4*)(p + tid * 4 + i * 1024) = v[i];
    }
}

// ---------------- launcher ----------------
extern "C" void kernel_launch(void* const* d_in, const int* in_sizes, int n_in,
                              void* d_out, int out_size)
{
    const float* query = (const float*)d_in[0];
    const float* key   = (const float*)d_in[1];
    const float* Wq = (const float*)d_in[3];
    const float* bq = (const float*)d_in[4];
    const float* Wk = (const float*)d_in[5];
    const float* bk = (const float*)d_in[6];
    float* out = (float*)d_out;

    __half *inhi, *inlo, *whi, *wlo, *ohi, *olo;
    cudaGetSymbolAddress((void**)&inhi, g_in_hi);
    cudaGetSymbolAddress((void**)&inlo, g_in_lo);
    cudaGetSymbolAddress((void**)&whi,  g_w_hi);
    cudaGetSymbolAddress((void**)&wlo,  g_w_lo);
    cudaGetSymbolAddress((void**)&ohi,  g_out_hi);
    cudaGetSymbolAddress((void**)&olo,  g_out_lo);

    cudaFuncSetAttribute(gemm_nt_mma, cudaFuncAttributeMaxDynamicSharedMemorySize, GEMM_SMEM);

    // 1) fused split of all four fp32 tensors into fp16 hi/lo pairs
    {
        int total = 2 * N4A + 2 * N4W;
        split_all<<<(total + 255) / 256, 256>>>(query, key, Wq, Wk, inhi, inlo, whi, wlo);
    }
    // 2) merged projections: z=0 -> Q = query@Wq^T+bq, z=1 -> K = key@Wk^T+bk
    {
        dim3 grid(D_MODEL / BN, N_TOK / BM, 2);
        gemm_nt_mma<<<grid, 512, GEMM_SMEM>>>(inhi, inlo, D_MODEL, ASZ,
                                              whi,  wlo,  D_MODEL, WSZ,
                                              bq, bk,
                                              nullptr, ohi, olo, D_MODEL, ASZ, D_MODEL);
    }
    // 3) energy in NCHUNK head-chunks on the main stream; each chunk's softmax
    //    runs on the side stream gated by an event -> overlaps next chunk's GEMM.
    const size_t HSZ = (size_t)N_TOK * N_TOK;           // per-head score elems
    for (int c = 0; c < NCHUNK; c++) {
        dim3 grid(N_TOK / BN, N_TOK / BM, HPC);
        const size_t ho = (size_t)c * HPC * HEAD_DIM;   // head column offset
        gemm_nt_mma<<<grid, 512, GEMM_SMEM>>>(ohi + ho,       olo + ho,       D_MODEL, HEAD_DIM,
                                              ohi + ASZ + ho, olo + ASZ + ho, D_MODEL, HEAD_DIM,
                                              nullptr, nullptr,
                                              out + (size_t)c * HPC * HSZ, nullptr, nullptr,
                                              N_TOK, HSZ, HEAD_DIM);
        cudaEventRecord(g_evg[c], 0);
    }
    for (int c = 0; c < NCHUNK; c++) {
        cudaStreamWaitEvent(g_s2, g_evg[c], 0);
        softmax_rows<<<HPC * N_TOK, 256, 0, g_s2>>>(out + (size_t)c * HPC * HSZ);
    }
    cudaEventRecord(g_evs, g_s2);
    cudaStreamWaitEvent(0, g_evs, 0);                   // join side stream
}

// round 16
// speedup vs baseline: 1.1777x; 1.0002x over previous
#include <cuda_runtime.h>
#include <cuda_fp16.h>
#include <math_constants.h>
#include <cstdint>

#define N_TOK    3072
#define D_MODEL  2048
#define N_HEADS  16
#define HEAD_DIM 128
#define NCHUNK   4
#define HPC      (N_HEADS / NCHUNK)   // heads per chunk = 4

// ---------------- device scratch (allocation-free rule) ----------------
// batched [2]: index 0 = query-side, 1 = key-side
__device__ __half g_in_hi[2][N_TOK * D_MODEL];
__device__ __half g_in_lo[2][N_TOK * D_MODEL];
__device__ __half g_w_hi[2][D_MODEL * D_MODEL];
__device__ __half g_w_lo[2][D_MODEL * D_MODEL];
__device__ __half g_out_hi[2][N_TOK * D_MODEL];
__device__ __half g_out_lo[2][N_TOK * D_MODEL];

// ---------------- second stream + events (pre-main init; no device mem) ----
static cudaStream_t g_s2;
static cudaEvent_t  g_evg[NCHUNK];
static cudaEvent_t  g_evs;
namespace {
struct StreamInit {
    StreamInit() {
        cudaStreamCreateWithFlags(&g_s2, cudaStreamNonBlocking);
        for (int i = 0; i < NCHUNK; i++)
            cudaEventCreateWithFlags(&g_evg[i], cudaEventDisableTiming);
        cudaEventCreateWithFlags(&g_evs, cudaEventDisableTiming);
    }
};
StreamInit g_stream_init;
}

// ---------------- helpers ----------------
__device__ __forceinline__ uint32_t smem_u32(const void* p) {
    uint32_t a;
    asm("{ .reg .u64 t; cvta.to.shared.u64 t, %1; cvt.u32.u64 %0, t; }" : "=r"(a) : "l"(p));
    return a;
}
#define CP_ASYNC16(dst, src) \
    asm volatile("cp.async.cg.shared.global [%0], [%1], 16;" :: "r"(dst), "l"(src) : "memory")
#define CP_COMMIT() asm volatile("cp.async.commit_group;" ::: "memory")
#define CP_WAIT1()  asm volatile("cp.async.wait_group 1;" ::: "memory")
#define CP_WAIT0()  asm volatile("cp.async.wait_group 0;" ::: "memory")

#define LDSM_X4(r0, r1, r2, r3, addr) \
    asm volatile("ldmatrix.sync.aligned.m8n8.x4.shared.b16 {%0,%1,%2,%3}, [%4];" \
                 : "=r"(r0), "=r"(r1), "=r"(r2), "=r"(r3) : "r"(addr))

// m16n8k16 fp16 MMA, fp32 accumulate
__device__ __forceinline__ void mma_16816(float* d, const uint32_t* a, const uint32_t* b) {
    asm volatile(
        "mma.sync.aligned.m16n8k16.row.col.f32.f16.f16.f32 "
        "{%0,%1,%2,%3}, {%4,%5,%6,%7}, {%8,%9}, {%0,%1,%2,%3};"
        : "+f"(d[0]), "+f"(d[1]), "+f"(d[2]), "+f"(d[3])
        : "r"(a[0]), "r"(a[1]), "r"(a[2]), "r"(a[3]), "r"(b[0]), "r"(b[1]));
}

// ---------------- fused split: all four fp32 tensors -> fp16 hi/lo ----------------
#define ASZ ((size_t)N_TOK * D_MODEL)
#define WSZ ((size_t)D_MODEL * D_MODEL)
#define N4A (int)(ASZ / 4)
#define N4W (int)(WSZ / 4)

__global__ void split_all(const float* __restrict__ query, const float* __restrict__ key,
                          const float* __restrict__ Wq,    const float* __restrict__ Wk,
                          __half* __restrict__ inhi, __half* __restrict__ inlo,
                          __half* __restrict__ whi,  __half* __restrict__ wlo)
{
    int i = blockIdx.x * blockDim.x + threadIdx.x;
    const float* src; __half* hi; __half* lo; int base;
    if (i < N4A)                    { src = query; hi = inhi;           lo = inlo;           base = i; }
    else if (i < 2 * N4A)           { src = key;   hi = inhi + ASZ;     lo = inlo + ASZ;     base = i - N4A; }
    else if (i < 2 * N4A + N4W)     { src = Wq;    hi = whi;            lo = wlo;            base = i - 2 * N4A; }
    else if (i < 2 * (N4A + N4W))   { src = Wk;    hi = whi + WSZ;      lo = wlo + WSZ;      base = i - 2 * N4A - N4W; }
    else return;

    float4 v = ((const float4*)src)[base];
    __half h0 = __float2half_rn(v.x), h1 = __float2half_rn(v.y);
    __half h2 = __float2half_rn(v.z), h3 = __float2half_rn(v.w);
    __half l0 = __float2half_rn(v.x - __half2float(h0));
    __half l1 = __float2half_rn(v.y - __half2float(h1));
    __half l2 = __float2half_rn(v.z - __half2float(h2));
    __half l3 = __float2half_rn(v.w - __half2float(h3));
    __half2* hp = (__half2*)hi;
    __half2* lp = (__half2*)lo;
    hp[base * 2 + 0] = __half2(h0, h1);
    hp[base * 2 + 1] = __half2(h2, h3);
    lp[base * 2 + 0] = __half2(l0, l1);
    lp[base * 2 + 1] = __half2(l2, l3);
}

// ---------------- NT GEMM: C = A*B^T (+bias), fp16-split x 3-MMA ----------------
// CTA 128x256, 16 warps (2x8 grid of 64x32 warp tiles), BK=32, 3-stage ring.
#define BM 128
#define BN 256
#define BK 32
#define RS 40                             // padded row stride (halves); 80B rows
#define ABYTES (BM * RS * 2)              // 10240 B per A tensor tile
#define BBYTES (BN * RS * 2)              // 20480 B per B tensor tile
#define STG_SZ (2 * ABYTES + 2 * BBYTES)  // 61440
#define SM_STG 1024                       // bias floats live in [0,1024)
#define GEMM_SMEM (SM_STG + 3 * STG_SZ)   // 185344 B
#define TILE16 (16 * RS * 2)              // byte stride of 16 rows = 1280

extern __shared__ char smem_raw[];

__global__ __launch_bounds__(512, 1)
void gemm_nt_mma(const __half* __restrict__ Ahi, const __half* __restrict__ Alo,
                 int lda, size_t aZ,
                 const __half* __restrict__ Bhi, const __half* __restrict__ Blo,
                 int ldb, size_t bZ,
                 const float* __restrict__ bias, const float* __restrict__ bias2,
                 float* __restrict__ Cf,
                 __half* __restrict__ Chi, __half* __restrict__ Clo,
                 int ldc, size_t cZ, int K)
{
    const int tid  = threadIdx.x;
    const int lane = tid & 31;
    const int wid  = tid >> 5;          // 0..15
    const int g    = lane >> 2;         // 0..7
    const int t    = lane & 3;          // 0..3
    const int wm   = (wid >> 3) * 64;   // warp row offset in CTA tile
    const int wn   = (wid & 7) * 32;    // warp col offset

    const int rowA0 = blockIdx.y * BM;
    const int rowB0 = blockIdx.x * BN;

    Ahi += (size_t)blockIdx.z * aZ;  Alo += (size_t)blockIdx.z * aZ;
    Bhi += (size_t)blockIdx.z * bZ;  Blo += (size_t)blockIdx.z * bZ;
    const float* biasz = (blockIdx.z && bias2) ? bias2 : bias;

    uint32_t sb = smem_u32(smem_raw);
    float* sbias = (float*)smem_raw;
    if (biasz && tid < BN) sbias[tid] = biasz[rowB0 + tid];

    // ldmatrix lane address offsets (bytes), relative to tensor tile base.
    const uint32_t aOff = (uint32_t)((wm + (lane & 15)) * RS + ((lane >> 4) << 3)) * 2;
    const int rfo = (lane & 7) + ((lane >> 1) & 8);   // (lane&16)?8:0
    const uint32_t bOff = (uint32_t)((wn + rfo) * RS + (lane & 8)) * 2;

    const int nc = K / BK;

    // fill one BK=32 chunk: A tensors 2x(128x4) + B tensors 2x(256x4) 16B chunks
    auto fill = [&](int c, int s) {
        uint32_t stBase = sb + SM_STG + s * STG_SZ;
        const __half* aSrc[2] = { Ahi + (size_t)rowA0 * lda + c * BK,
                                  Alo + (size_t)rowA0 * lda + c * BK };
        const __half* bSrc[2] = { Bhi + (size_t)rowB0 * ldb + c * BK,
                                  Blo + (size_t)rowB0 * ldb + c * BK };
#pragma unroll
        for (int rep = 0; rep < 2; rep++) {
            int idx = rep * 512 + tid;       // 0..1023
            int ten = idx >> 9;              // 0..1 (Ah, Al)
            int r   = (idx >> 2) & 127;
            int c16 = idx & 3;
            uint32_t dst = stBase + (uint32_t)(ten * ABYTES + r * (RS * 2) + c16 * 16);
            CP_ASYNC16(dst, aSrc[ten] + (size_t)r * lda + c16 * 8);
        }
#pragma unroll
        for (int rep = 0; rep < 4; rep++) {
            int idx = rep * 512 + tid;       // 0..2047
            int ten = idx >> 10;             // 0..1 (Bh, Bl)
            int r   = (idx >> 2) & 255;
            int c16 = idx & 3;
            uint32_t dst = stBase + (uint32_t)(2 * ABYTES + ten * BBYTES + r * (RS * 2) + c16 * 16);
            CP_ASYNC16(dst, bSrc[ten] + (size_t)r * ldb + c16 * 8);
        }
        CP_COMMIT();
    };

    fill(0, 0);
    if (nc > 1) fill(1, 1);

    float acc[4][4][4];
#pragma unroll
    for (int i = 0; i < 4; i++)
#pragma unroll
        for (int j = 0; j < 4; j++)
#pragma unroll
            for (int e = 0; e < 4; e++) acc[i][j][e] = 0.f;

    for (int c = 0; c < nc; c++) {
        if (c + 1 < nc) CP_WAIT1(); else CP_WAIT0();
        __syncthreads();                       // fill(c) visible; stage (c+2)%3 free
        if (c + 2 < nc) fill(c + 2, (c + 2) % 3);

        uint32_t stBase = sb + SM_STG + (c % 3) * STG_SZ;
        uint32_t bAh = stBase;
        uint32_t bAl = stBase + ABYTES;
        uint32_t bBh = stBase + 2 * ABYTES;
        uint32_t bBl = stBase + 2 * ABYTES + BBYTES;

#pragma unroll
        for (int ks = 0; ks < BK / 16; ks++) {
            uint32_t ah[4][4], al[4][4], bh[4][2], bl[4][2];
#pragma unroll
            for (int i = 0; i < 4; i++) {
                uint32_t off = aOff + i * TILE16 + ks * 32;
                LDSM_X4(ah[i][0], ah[i][1], ah[i][2], ah[i][3], bAh + off);
                LDSM_X4(al[i][0], al[i][1], al[i][2], al[i][3], bAl + off);
            }
#pragma unroll
            for (int jj = 0; jj < 2; jj++) {
                uint32_t off = bOff + jj * TILE16 + ks * 32;
                LDSM_X4(bh[2*jj][0], bh[2*jj][1], bh[2*jj+1][0], bh[2*jj+1][1], bBh + off);
                LDSM_X4(bl[2*jj][0], bl[2*jj][1], bl[2*jj+1][0], bl[2*jj+1][1], bBl + off);
            }
#pragma unroll
            for (int i = 0; i < 4; i++)
#pragma unroll
                for (int j = 0; j < 4; j++) {
                    mma_16816(acc[i][j], ah[i], bh[j]);
                    mma_16816(acc[i][j], ah[i], bl[j]);
                    mma_16816(acc[i][j], al[i], bh[j]);
                }
        }
    }

    // ---------------- epilogue ----------------
#pragma unroll
    for (int i = 0; i < 4; i++) {
#pragma unroll
        for (int j = 0; j < 4; j++) {
            int row = rowA0 + wm + i * 16 + g;
            int col = rowB0 + wn + j * 8 + 2 * t;
            if (Cf) {
                float* base = Cf + (size_t)blockIdx.z * cZ;
                float2 v0 = { acc[i][j][0], acc[i][j][1] };
                float2 v1 = { acc[i][j][2], acc[i][j][3] };
                *(float2*)(base + (size_t)row * ldc + col)       = v0;
                *(float2*)(base + (size_t)(row + 8) * ldc + col) = v1;
            } else {
                float b0 = biasz ? sbias[wn + j * 8 + 2 * t]     : 0.f;
                float b1 = biasz ? sbias[wn + j * 8 + 2 * t + 1] : 0.f;
                float x0 = acc[i][j][0] + b0, x1 = acc[i][j][1] + b1;
                float x2 = acc[i][j][2] + b0, x3 = acc[i][j][3] + b1;
                __half h0 = __float2half_rn(x0), h1 = __float2half_rn(x1);
                __half h2 = __float2half_rn(x2), h3 = __float2half_rn(x3);
                __half l0 = __float2half_rn(x0 - __half2float(h0));
                __half l1 = __float2half_rn(x1 - __half2float(h1));
                __half l2 = __float2half_rn(x2 - __half2float(h2));
                __half l3 = __float2half_rn(x3 - __half2float(h3));
                size_t zo = (size_t)blockIdx.z * cZ;
                size_t o0 = zo + (size_t)row * ldc + col;
                size_t o1 = zo + (size_t)(row + 8) * ldc + col;
                *(__half2*)(Chi + o0) = __half2(h0, h1);
                *(__half2*)(Chi + o1) = __half2(h2, h3);
                *(__half2*)(Clo + o0) = __half2(l0, l1);
                *(__half2*)(Clo + o1) = __half2(l2, l3);
            }
        }
    }
}

// ---------------- softmax: one block per row, row in registers ----------------
__global__ __launch_bounds__(256)
void softmax_rows(float* __restrict__ data)
{
    float* p = data + (size_t)blockIdx.x * N_TOK;
    const int tid = threadIdx.x;

    float4 v[3];
    float mx = -CUDART_INF_F;
#pragma unroll
    for (int i = 0; i < 3; i++) {
        v[i] = __ldcs((const float4*)(p + tid * 4 + i * 1024));
        mx = fmaxf(mx, fmaxf(fmaxf(v[i].x, v[i].y), fmaxf(v[i].z, v[i].w)));
    }

    __shared__ float sred[8];
#pragma unroll
    for (int o = 16; o; o >>= 1) mx = fmaxf(mx, __shfl_xor_sync(0xffffffffu, mx, o));
    if ((tid & 31) == 0) sred[tid >> 5] = mx;
    __syncthreads();
    {
        float m = sred[tid & 7];
#pragma unroll
        for (int o = 4; o; o >>= 1) m = fmaxf(m, __shfl_xor_sync(0xffffffffu, m, o));
        mx = m;
    }
    __syncthreads();

    float sum = 0.f;
#pragma unroll
    for (int i = 0; i < 3; i++) {
        v[i].x = __expf(v[i].x - mx); sum += v[i].x;
        v[i].y = __expf(v[i].y - mx); sum += v[i].y;
        v[i].z = __expf(v[i].z - mx); sum += v[i].z;
        v[i].w = __expf(v[i].w - mx); sum += v[i].w;
    }
#pragma unroll
    for (int o = 16; o; o >>= 1) sum += __shfl_xor_sync(0xffffffffu, sum, o);
    if ((tid & 31) == 0) sred[tid >> 5] = sum;
    __syncthreads();
    {
        float s = sred[tid & 7];
#pragma unroll
        for (int o = 4; o; o >>= 1) s += __shfl_xor_sync(0xffffffffu, s, o);
        sum = s;
    }

    const float inv = 1.0f / sum;
#pragma unroll
    for (int i = 0; i < 3; i++) {
        v[i].x *= inv; v[i].y *= inv; v[i].z *= inv; v[i].w *= inv;
        *(float4*)(p + tid * 4 + i * 1024) = v[i];
    }
}

// ---------------- launcher ----------------
extern "C" void kernel_launch(void* const* d_in, const int* in_sizes, int n_in,
                              void* d_out, int out_size)
{
    const float* query = (const float*)d_in[0];
    const float* key   = (const float*)d_in[1];
    const float* Wq = (const float*)d_in[3];
    const float* bq = (const float*)d_in[4];
    const float* Wk = (const float*)d_in[5];
    const float* bk = (const float*)d_in[6];
    float* out = (float*)d_out;

    __half *inhi, *inlo, *whi, *wlo, *ohi, *olo;
    cudaGetSymbolAddress((void**)&inhi, g_in_hi);
    cudaGetSymbolAddress((void**)&inlo, g_in_lo);
    cudaGetSymbolAddress((void**)&whi,  g_w_hi);
    cudaGetSymbolAddress((void**)&wlo,  g_w_lo);
    cudaGetSymbolAddress((void**)&ohi,  g_out_hi);
    cudaGetSymbolAddress((void**)&olo,  g_out_lo);

    cudaFuncSetAttribute(gemm_nt_mma, cudaFuncAttributeMaxDynamicSharedMemorySize, GEMM_SMEM);

    // 1) fused split of all four fp32 tensors into fp16 hi/lo pairs
    {
        int total = 2 * N4A + 2 * N4W;
        split_all<<<(total + 255) / 256, 256>>>(query, key, Wq, Wk, inhi, inlo, whi, wlo);
    }
    // 2) merged projections: z=0 -> Q = query@Wq^T+bq, z=1 -> K = key@Wk^T+bk
    {
        dim3 grid(D_MODEL / BN, N_TOK / BM, 2);
        gemm_nt_mma<<<grid, 512, GEMM_SMEM>>>(inhi, inlo, D_MODEL, ASZ,
                                              whi,  wlo,  D_MODEL, WSZ,
                                              bq, bk,
                                              nullptr, ohi, olo, D_MODEL, ASZ, D_MODEL);
    }
    // 3) energy in NCHUNK head-chunks on the main stream; each chunk's softmax
    //    runs on the side stream gated by an event -> overlaps next chunk's GEMM.
    const size_t HSZ = (size_t)N_TOK * N_TOK;           // per-head score elems
    for (int c = 0; c < NCHUNK; c++) {
        dim3 grid(N_TOK / BN, N_TOK / BM, HPC);
        const size_t ho = (size_t)c * HPC * HEAD_DIM;   // head column offset
        gemm_nt_mma<<<grid, 512, GEMM_SMEM>>>(ohi + ho,       olo + ho,       D_MODEL, HEAD_DIM,
                                              ohi + ASZ + ho, olo + ASZ + ho, D_MODEL, HEAD_DIM,
                                              nullptr, nullptr,
                                              out + (size_t)c * HPC * HSZ, nullptr, nullptr,
                                              N_TOK, HSZ, HEAD_DIM);
        cudaEventRecord(g_evg[c], 0);
    }
    for (int c = 0; c < NCHUNK; c++) {
        cudaStreamWaitEvent(g_s2, g_evg[c], 0);
        softmax_rows<<<HPC * N_TOK, 256, 0, g_s2>>>(out + (size_t)c * HPC * HSZ);
    }
    cudaEventRecord(g_evs, g_s2);
    cudaStreamWaitEvent(0, g_evs, 0);                   // join side stream
}